// round 11
// baseline (speedup 1.0000x reference)
#include <cuda_runtime.h>
#include <cstdint>

// Perception3D: 7-point stencil, 5 output groups per input channel.
// in : [B=4, C=16, D=64, H=64, W=64] fp32
// out: [B=4, C*G=80, D=64, H=64, W=64] fp32, out channel = c*5+g
//   g=0 ident, g=1 6-neighbor sum, g=2 gx, g=3 gy, g=4 gz (zero-padded shifts)
//
// R11: persistent-chunk variant of R6. 592 CTAs (4/SM on 148 SMs); each CTA
// owns 14 CONSECUTIVE tiles (tile = 2048 input floats -> 5 x 8KB output), so
// each SM emits long sequential write runs (~112KB/plane) instead of
// scheduler-scattered 8KB bursts. v8.f32 loads + st.global.wt v8 stores.

#define Dz 64
#define Hy 64
#define Wx 64
#define PLANE (Dz * Hy * Wx)
#define ROW   Wx
#define SLAB  (Hy * Wx)
#define W8    (Wx / 8)
#define G 5

#define NTILES 8192               // total tiles (256 threads' work each)
#define NCTA   592                // 4 CTAs/SM * 148 SMs
#define CHUNK  14                 // ceil(8192/592)

__device__ __forceinline__ void ld8(const float* p, float* v) {
    asm("ld.global.nc.v8.f32 {%0,%1,%2,%3,%4,%5,%6,%7}, [%8];"
        : "=f"(v[0]), "=f"(v[1]), "=f"(v[2]), "=f"(v[3]),
          "=f"(v[4]), "=f"(v[5]), "=f"(v[6]), "=f"(v[7])
        : "l"(p));
}

__device__ __forceinline__ void ld8z(const float* p, float* v, bool ok) {
    if (ok) {
        ld8(p, v);
    } else {
#pragma unroll
        for (int i = 0; i < 8; i++) v[i] = 0.f;
    }
}

__device__ __forceinline__ void st8wt(float* p, const float* v) {
    asm volatile("st.global.wt.v8.f32 [%0], {%1,%2,%3,%4,%5,%6,%7,%8};"
        :: "l"(p),
           "f"(v[0]), "f"(v[1]), "f"(v[2]), "f"(v[3]),
           "f"(v[4]), "f"(v[5]), "f"(v[6]), "f"(v[7])
        : "memory");
}

__global__ void __launch_bounds__(256)
perception3d_kernel(const float* __restrict__ in, float* __restrict__ out) {
    unsigned t0 = blockIdx.x * CHUNK;
    unsigned t1 = t0 + CHUNK;
    if (t1 > NTILES) t1 = NTILES;

    for (unsigned tile = t0; tile < t1; tile++) {
        unsigned tid = tile * 256 + threadIdx.x;

        unsigned w8 = tid & (W8 - 1);          // 0..7
        unsigned h  = (tid >> 3) & (Hy - 1);   // 0..63
        unsigned d  = (tid >> 9) & (Dz - 1);   // 0..63
        unsigned bc = tid >> 15;               // 0..63

        const float* base = in + (size_t)bc * PLANE + (size_t)d * SLAB
                               + (size_t)h * ROW + (size_t)w8 * 8;

        float c[8], xp[8], xm[8], yp[8], ym[8];
        ld8(base, c);
        ld8z(base + SLAB, xp, d + 1 < Dz);
        ld8z(base - SLAB, xm, d >= 1);
        ld8z(base + ROW,  yp, h + 1 < Hy);
        ld8z(base - ROW,  ym, h >= 1);

        float nextv = (w8 + 1 < W8) ? __ldg(base + 8) : 0.f;
        float prevv = (w8 >= 1)     ? __ldg(base - 1) : 0.f;

        float zp[8], zm[8];
#pragma unroll
        for (int i = 0; i < 8; i++) {
            zp[i] = (i < 7) ? c[i + 1] : nextv;
            zm[i] = (i > 0) ? c[i - 1] : prevv;
        }

        float ns[8], gx[8], gy[8], gz[8];
#pragma unroll
        for (int i = 0; i < 8; i++) {
            ns[i] = xp[i] + xm[i] + yp[i] + ym[i] + zp[i] + zm[i];
            gx[i] = xp[i] - xm[i];
            gy[i] = yp[i] - ym[i];
            gz[i] = zp[i] - zm[i];
        }

        unsigned b  = bc >> 4;
        unsigned cc = bc & 15;
        size_t spatial = (size_t)d * SLAB + (size_t)h * ROW + (size_t)w8 * 8;
        float* ob = out + (size_t)b * (16 * G * PLANE)
                        + (size_t)(cc * G) * PLANE + spatial;

        st8wt(ob,             c);
        st8wt(ob + 1 * PLANE, ns);
        st8wt(ob + 2 * PLANE, gx);
        st8wt(ob + 3 * PLANE, gy);
        st8wt(ob + 4 * PLANE, gz);
    }
}

extern "C" void kernel_launch(void* const* d_in, const int* in_sizes, int n_in,
                              void* d_out, int out_size) {
    const float* in = (const float*)d_in[0];
    float* out = (float*)d_out;
    perception3d_kernel<<<NCTA, 256>>>(in, out);
}

// round 12
// speedup vs baseline: 1.2984x; 1.2984x over previous
#include <cuda_runtime.h>
#include <cstdint>

// Perception3D: 7-point stencil, 5 output groups per input channel.
// in : [B=4, C=16, D=64, H=64, W=64] fp32
// out: [B=4, C*G=80, D=64, H=64, W=64] fp32, out channel = c*5+g
//   g=0 ident, g=1 6-neighbor sum, g=2 gx, g=3 gy, g=4 gz (zero-padded shifts)
//
// FINAL (R6 config, best of 11 rounds): fused single kernel, one thread = 8
// consecutive floats along W; v8.f32 256-bit loads (LDG.E.256) +
// st.global.wt v8 stores (STG.E.256). 256-thread blocks, 8192 CTAs,
// wave-scheduled (flat grid).
//
// Roofline verdict: DRAM traffic == mandatory 335MB write footprint (input
// stays L2-resident). All variants — float4/v8, 1/2-row, .cs/.wt/TMA-bulk,
// 256/512 threads, store-order rotation, shuffle edge taps, group-split,
// persistent chunks — pin at 5.2-5.8 TB/s with the flat wave-scheduled
// many-stream pattern measurably best (~72% of 8TB/s spec = the chip's
// pure-write efficiency wall). 62.6us bench, reproduced.

#define Dz 64
#define Hy 64
#define Wx 64
#define PLANE (Dz * Hy * Wx)
#define ROW   Wx
#define SLAB  (Hy * Wx)
#define W8    (Wx / 8)
#define G 5

__device__ __forceinline__ void ld8(const float* p, float* v) {
    asm("ld.global.nc.v8.f32 {%0,%1,%2,%3,%4,%5,%6,%7}, [%8];"
        : "=f"(v[0]), "=f"(v[1]), "=f"(v[2]), "=f"(v[3]),
          "=f"(v[4]), "=f"(v[5]), "=f"(v[6]), "=f"(v[7])
        : "l"(p));
}

__device__ __forceinline__ void ld8z(const float* p, float* v, bool ok) {
    if (ok) {
        ld8(p, v);
    } else {
#pragma unroll
        for (int i = 0; i < 8; i++) v[i] = 0.f;
    }
}

__device__ __forceinline__ void st8wt(float* p, const float* v) {
    asm volatile("st.global.wt.v8.f32 [%0], {%1,%2,%3,%4,%5,%6,%7,%8};"
        :: "l"(p),
           "f"(v[0]), "f"(v[1]), "f"(v[2]), "f"(v[3]),
           "f"(v[4]), "f"(v[5]), "f"(v[6]), "f"(v[7])
        : "memory");
}

__global__ void __launch_bounds__(256)
perception3d_kernel(const float* __restrict__ in, float* __restrict__ out) {
    // tid over BC * D * H * W8 = 64*64*64*8 = 2,097,152
    unsigned tid = blockIdx.x * blockDim.x + threadIdx.x;

    unsigned w8 = tid & (W8 - 1);          // 0..7
    unsigned h  = (tid >> 3) & (Hy - 1);   // 0..63
    unsigned d  = (tid >> 9) & (Dz - 1);   // 0..63
    unsigned bc = tid >> 15;               // 0..63

    const float* base = in + (size_t)bc * PLANE + (size_t)d * SLAB + (size_t)h * ROW + (size_t)w8 * 8;

    float c[8], xp[8], xm[8], yp[8], ym[8];
    ld8(base, c);
    ld8z(base + SLAB, xp, d + 1 < Dz);
    ld8z(base - SLAB, xm, d >= 1);
    ld8z(base + ROW,  yp, h + 1 < Hy);
    ld8z(base - ROW,  ym, h >= 1);

    float nextv = (w8 + 1 < W8) ? __ldg(base + 8) : 0.f;
    float prevv = (w8 >= 1)     ? __ldg(base - 1) : 0.f;

    float zp[8], zm[8];
#pragma unroll
    for (int i = 0; i < 8; i++) {
        zp[i] = (i < 7) ? c[i + 1] : nextv;
        zm[i] = (i > 0) ? c[i - 1] : prevv;
    }

    float ns[8], gx[8], gy[8], gz[8];
#pragma unroll
    for (int i = 0; i < 8; i++) {
        ns[i] = xp[i] + xm[i] + yp[i] + ym[i] + zp[i] + zm[i];
        gx[i] = xp[i] - xm[i];
        gy[i] = yp[i] - ym[i];
        gz[i] = zp[i] - zm[i];
    }

    unsigned b  = bc >> 4;
    unsigned cc = bc & 15;
    size_t spatial = (size_t)d * SLAB + (size_t)h * ROW + (size_t)w8 * 8;
    float* ob = out + (size_t)b * (16 * G * PLANE) + (size_t)(cc * G) * PLANE + spatial;

    st8wt(ob,             c);
    st8wt(ob + 1 * PLANE, ns);
    st8wt(ob + 2 * PLANE, gx);
    st8wt(ob + 3 * PLANE, gy);
    st8wt(ob + 4 * PLANE, gz);
}

extern "C" void kernel_launch(void* const* d_in, const int* in_sizes, int n_in,
                              void* d_out, int out_size) {
    const float* in = (const float*)d_in[0];
    float* out = (float*)d_out;
    // 2,097,152 threads / 256 = 8192 blocks
    perception3d_kernel<<<8192, 256>>>(in, out);
}

// round 13
// speedup vs baseline: 1.3231x; 1.0190x over previous
#include <cuda_runtime.h>
#include <cstdint>

// Perception3D: 7-point stencil, 5 output groups per input channel.
// in : [B=4, C=16, D=64, H=64, W=64] fp32
// out: [B=4, C*G=80, D=64, H=64, W=64] fp32, out channel = c*5+g
//   g=0 ident, g=1 6-neighbor sum, g=2 gx, g=3 gy, g=4 gz (zero-padded shifts)
//
// FINAL (R6 config, best of 12 rounds): fused single kernel, one thread = 8
// consecutive floats along W; v8.f32 256-bit loads (LDG.E.256) +
// st.global.wt v8 stores (STG.E.256). 256-thread blocks, 8192 CTAs,
// flat wave-scheduled grid.
//
// Roofline verdict: DRAM traffic == mandatory 335MB write footprint (input
// stays L2-resident across replays). Every variant tested — float4/v8,
// 1/2-row per thread, .cs/.wt/TMA-bulk stores, 256/512 threads, store-order
// rotation, shuffle edge taps, group-split, persistent chunks — lands at
// 5.2-5.8 TB/s DRAM-active, with this flat many-stream pattern best at
// ~72% of the 8TB/s spec: the chip's pure-write HBM efficiency wall.
// Kernel 60.0us (stable to 0.1us); bench 62.6-63.5us (replay noise).

#define Dz 64
#define Hy 64
#define Wx 64
#define PLANE (Dz * Hy * Wx)
#define ROW   Wx
#define SLAB  (Hy * Wx)
#define W8    (Wx / 8)
#define G 5

__device__ __forceinline__ void ld8(const float* p, float* v) {
    asm("ld.global.nc.v8.f32 {%0,%1,%2,%3,%4,%5,%6,%7}, [%8];"
        : "=f"(v[0]), "=f"(v[1]), "=f"(v[2]), "=f"(v[3]),
          "=f"(v[4]), "=f"(v[5]), "=f"(v[6]), "=f"(v[7])
        : "l"(p));
}

__device__ __forceinline__ void ld8z(const float* p, float* v, bool ok) {
    if (ok) {
        ld8(p, v);
    } else {
#pragma unroll
        for (int i = 0; i < 8; i++) v[i] = 0.f;
    }
}

__device__ __forceinline__ void st8wt(float* p, const float* v) {
    asm volatile("st.global.wt.v8.f32 [%0], {%1,%2,%3,%4,%5,%6,%7,%8};"
        :: "l"(p),
           "f"(v[0]), "f"(v[1]), "f"(v[2]), "f"(v[3]),
           "f"(v[4]), "f"(v[5]), "f"(v[6]), "f"(v[7])
        : "memory");
}

__global__ void __launch_bounds__(256)
perception3d_kernel(const float* __restrict__ in, float* __restrict__ out) {
    // tid over BC * D * H * W8 = 64*64*64*8 = 2,097,152
    unsigned tid = blockIdx.x * blockDim.x + threadIdx.x;

    unsigned w8 = tid & (W8 - 1);          // 0..7
    unsigned h  = (tid >> 3) & (Hy - 1);   // 0..63
    unsigned d  = (tid >> 9) & (Dz - 1);   // 0..63
    unsigned bc = tid >> 15;               // 0..63

    const float* base = in + (size_t)bc * PLANE + (size_t)d * SLAB + (size_t)h * ROW + (size_t)w8 * 8;

    float c[8], xp[8], xm[8], yp[8], ym[8];
    ld8(base, c);
    ld8z(base + SLAB, xp, d + 1 < Dz);
    ld8z(base - SLAB, xm, d >= 1);
    ld8z(base + ROW,  yp, h + 1 < Hy);
    ld8z(base - ROW,  ym, h >= 1);

    float nextv = (w8 + 1 < W8) ? __ldg(base + 8) : 0.f;
    float prevv = (w8 >= 1)     ? __ldg(base - 1) : 0.f;

    float zp[8], zm[8];
#pragma unroll
    for (int i = 0; i < 8; i++) {
        zp[i] = (i < 7) ? c[i + 1] : nextv;
        zm[i] = (i > 0) ? c[i - 1] : prevv;
    }

    float ns[8], gx[8], gy[8], gz[8];
#pragma unroll
    for (int i = 0; i < 8; i++) {
        ns[i] = xp[i] + xm[i] + yp[i] + ym[i] + zp[i] + zm[i];
        gx[i] = xp[i] - xm[i];
        gy[i] = yp[i] - ym[i];
        gz[i] = zp[i] - zm[i];
    }

    unsigned b  = bc >> 4;
    unsigned cc = bc & 15;
    size_t spatial = (size_t)d * SLAB + (size_t)h * ROW + (size_t)w8 * 8;
    float* ob = out + (size_t)b * (16 * G * PLANE) + (size_t)(cc * G) * PLANE + spatial;

    st8wt(ob,             c);
    st8wt(ob + 1 * PLANE, ns);
    st8wt(ob + 2 * PLANE, gx);
    st8wt(ob + 3 * PLANE, gy);
    st8wt(ob + 4 * PLANE, gz);
}

extern "C" void kernel_launch(void* const* d_in, const int* in_sizes, int n_in,
                              void* d_out, int out_size) {
    const float* in = (const float*)d_in[0];
    float* out = (float*)d_out;
    // 2,097,152 threads / 256 = 8192 blocks
    perception3d_kernel<<<8192, 256>>>(in, out);
}